// round 5
// baseline (speedup 1.0000x reference)
#include <cuda_runtime.h>
#include <cuda_bf16.h>

#define NUM_NODES 20000
#define NUM_EDGES 640000
#define NODE 128
#define ESZ 20
#define F3 384          // 3 * NODE

// scratch: scalar_output = silu(ns@W1+b1)@W2+b2, [NUM_NODES, 384]
__device__ float g_so[NUM_NODES * F3];

// ---------------------------------------------------------------------------
// Kernel 0: initialize output with the input node states (result = input + msum)
// out layout: [NUM_NODES*128] scalar followed by [NUM_NODES*3*128] vector
// ---------------------------------------------------------------------------
__global__ void init_out_kernel(const float4* __restrict__ nss,
                                const float4* __restrict__ nsv,
                                float4* __restrict__ out) {
    const int ns4 = NUM_NODES * NODE / 4;             // 640000
    const int tot4 = ns4 + NUM_NODES * 3 * NODE / 4;  // 2560000
    for (int i = blockIdx.x * blockDim.x + threadIdx.x; i < tot4;
         i += gridDim.x * blockDim.x) {
        out[i] = (i < ns4) ? nss[i] : nsv[i - ns4];
    }
}

// ---------------------------------------------------------------------------
// Kernel 1: node MLP -> g_so
// block = 128 threads, NB=8 nodes per block (weights amortized over 8 rows)
// ---------------------------------------------------------------------------
#define NB 8
__global__ __launch_bounds__(128) void node_mlp_kernel(
    const float* __restrict__ ns, const float* __restrict__ W1,
    const float* __restrict__ b1, const float* __restrict__ W2,
    const float* __restrict__ b2) {
    __shared__ float xs[NB][NODE];
    __shared__ float hs[NB][NODE];
    const int tid = threadIdx.x;
    const int base = blockIdx.x * NB;

    #pragma unroll
    for (int n = 0; n < NB; n++)
        xs[n][tid] = ns[(base + n) * NODE + tid];
    __syncthreads();

    // h = silu(x @ W1 + b1)
    {
        float acc[NB];
        const float bb = b1[tid];
        #pragma unroll
        for (int n = 0; n < NB; n++) acc[n] = bb;
        #pragma unroll 4
        for (int k = 0; k < NODE; k++) {
            const float w = W1[k * NODE + tid];
            #pragma unroll
            for (int n = 0; n < NB; n++) acc[n] = fmaf(xs[n][k], w, acc[n]);
        }
        #pragma unroll
        for (int n = 0; n < NB; n++) {
            const float a = acc[n];
            hs[n][tid] = a / (1.0f + __expf(-a));   // silu
        }
    }
    __syncthreads();

    // so = h @ W2 + b2   (384 outputs, 3 per thread)
    #pragma unroll
    for (int jj = 0; jj < 3; jj++) {
        const int j = tid + jj * NODE;
        float acc[NB];
        const float bb = b2[j];
        #pragma unroll
        for (int n = 0; n < NB; n++) acc[n] = bb;
        #pragma unroll 4
        for (int k = 0; k < NODE; k++) {
            const float w = W2[k * F3 + j];
            #pragma unroll
            for (int n = 0; n < NB; n++) acc[n] = fmaf(hs[n][k], w, acc[n]);
        }
        #pragma unroll
        for (int n = 0; n < NB; n++)
            g_so[(base + n) * F3 + j] = acc[n];
    }
}

// ---------------------------------------------------------------------------
// helpers
// ---------------------------------------------------------------------------
__device__ __forceinline__ void red4(float* p, float4 v) {
    asm volatile("red.global.add.v4.f32 [%0], {%1,%2,%3,%4};"
                 :: "l"(p), "f"(v.x), "f"(v.y), "f"(v.z), "f"(v.w)
                 : "memory");
}
__device__ __forceinline__ float4 fma4(float a, float4 b, float4 c) {
    return make_float4(fmaf(a, b.x, c.x), fmaf(a, b.y, c.y),
                       fmaf(a, b.z, c.z), fmaf(a, b.w, c.w));
}
__device__ __forceinline__ float4 mul4(float4 a, float4 b) {
    return make_float4(a.x * b.x, a.y * b.y, a.z * b.z, a.w * b.w);
}
__device__ __forceinline__ float4 scale4(float4 a, float s) {
    return make_float4(a.x * s, a.y * s, a.z * s, a.w * s);
}

// ---------------------------------------------------------------------------
// Kernel 2: edge filter GEMM + gating + vectorized reduction scatter
//   - Wf (30 KB), bf, and a 128-edge edge_state tile staged in smem once/block
//   - 8 warps x 4 rounds x 4 edges = 128 edges per block
//   - each warp keeps a 4-edge x 12-col float4 register tile, so every smem
//     read of a Wf row is reused 4x; Wf staging amortized over 128 edges
// ---------------------------------------------------------------------------
#define TE 128                 // edges per block
#define WE 4                   // edges per warp per round
#define ROUNDS 4               // 8 warps * 4 edges * 4 rounds = 128

__global__ __launch_bounds__(256) void edge_kernel(
    const float* __restrict__ nss, const float* __restrict__ nsv,
    const float* __restrict__ est, const float* __restrict__ evec,
    const float* __restrict__ edist, const int* __restrict__ edges,
    const float* __restrict__ Wf, const float* __restrict__ bf,
    float* __restrict__ out) {
    __shared__ float4 sWf[ESZ * 96];   // 20 rows x 96 float4 = 30720 B
    __shared__ float4 sBf[96];         // 1536 B
    __shared__ float  sEs[TE * ESZ];   // 10240 B

    const int tid = threadIdx.x;
    const int warp = tid >> 5;
    const int lane = tid & 31;
    const int eblock = blockIdx.x * TE;

    // cooperative staging (all loads coalesced)
    {
        const float4* wf4 = (const float4*)Wf;
        #pragma unroll
        for (int i = tid; i < ESZ * 96; i += 256) sWf[i] = wf4[i];
        if (tid < 96) sBf[tid] = ((const float4*)bf)[tid];
        #pragma unroll
        for (int i = tid; i < TE * ESZ; i += 256) sEs[i] = est[eblock * ESZ + i];
    }
    __syncthreads();

    const int c = lane * 4;  // column base within each 128-wide chunk
    float* outv = out + (long)NUM_NODES * NODE;

    for (int r = 0; r < ROUNDS; r++) {
        const int elocal = r * 32 + warp * WE;   // first local edge this warp

        // accumulators: WE edges x 3 chunks, init with bias
        float4 a0[WE], a1[WE], a2[WE];
        {
            const float4 b0 = sBf[lane], b1v = sBf[32 + lane], b2v = sBf[64 + lane];
            #pragma unroll
            for (int i = 0; i < WE; i++) { a0[i] = b0; a1[i] = b1v; a2[i] = b2v; }
        }

        // filter GEMM: fw = es @ Wf + bf
        #pragma unroll
        for (int k = 0; k < ESZ; k++) {
            const float4 w0 = sWf[k * 96 + lane];
            const float4 w1 = sWf[k * 96 + 32 + lane];
            const float4 w2 = sWf[k * 96 + 64 + lane];
            #pragma unroll
            for (int i = 0; i < WE; i++) {
                const float ek = sEs[(elocal + i) * ESZ + k];   // smem broadcast
                a0[i] = fma4(ek, w0, a0[i]);
                a1[i] = fma4(ek, w1, a1[i]);
                a2[i] = fma4(ek, w2, a2[i]);
            }
        }

        // epilogue: gating + scatter, per edge
        #pragma unroll
        for (int i = 0; i < WE; i++) {
            const long e = (long)eblock + elocal + i;
            const int src = __ldg(&edges[2 * e]);
            const int dst = __ldg(&edges[2 * e + 1]);

            const float d = __ldg(&edist[e]);
            const float cut = (d < 5.0f)
                ? 0.5f * (__cosf(d * (3.14159265358979f / 5.0f)) + 1.0f) : 0.0f;

            const float v0 = __ldg(&evec[e * 3 + 0]);
            const float v1 = __ldg(&evec[e * 3 + 1]);
            const float v2 = __ldg(&evec[e * 3 + 2]);
            const float nrm = sqrtf(v0 * v0 + v1 * v1 + v2 * v2);
            const float inv = 1.0f / fmaxf(nrm, 1e-12f);
            const float env0 = v0 * inv, env1 = v1 * inv, env2 = v2 * inv;

            // filter_output = fw * cut * scalar_output[src]  (cut folded)
            const float4* sop = (const float4*)&g_so[(long)src * F3];
            const float4 fo0 = mul4(a0[i], scale4(sop[lane],      cut)); // gate_state_vector
            const float4 fo1 = mul4(a1[i], scale4(sop[32 + lane], cut)); // gate_edge_vector
            const float4 fo2 = mul4(a2[i], scale4(sop[64 + lane], cut)); // gate_node_state

            // scalar message
            const float4 nssv = ((const float4*)&nss[(long)src * NODE])[lane];
            red4(&out[(long)dst * NODE + c], mul4(nssv, fo2));

            // vector messages
            const float4* nvp = (const float4*)&nsv[(long)src * 3 * NODE];
            {
                float4 m = mul4(nvp[lane], fo0);      m = fma4(env0, fo1, m);
                red4(&outv[(long)dst * 3 * NODE + 0 * NODE + c], m);
            }
            {
                float4 m = mul4(nvp[32 + lane], fo0); m = fma4(env1, fo1, m);
                red4(&outv[(long)dst * 3 * NODE + 1 * NODE + c], m);
            }
            {
                float4 m = mul4(nvp[64 + lane], fo0); m = fma4(env2, fo1, m);
                red4(&outv[(long)dst * 3 * NODE + 2 * NODE + c], m);
            }
        }
    }
}

// ---------------------------------------------------------------------------
extern "C" void kernel_launch(void* const* d_in, const int* in_sizes, int n_in,
                              void* d_out, int out_size) {
    const float* nss   = (const float*)d_in[0];   // [20000,128]
    const float* nsv   = (const float*)d_in[1];   // [20000,3,128]
    const float* est   = (const float*)d_in[2];   // [640000,20]
    const float* evec  = (const float*)d_in[3];   // [640000,3]
    const float* edist = (const float*)d_in[4];   // [640000,1]
    const int*   edges = (const int*)d_in[5];     // [640000,2]
    const float* Wf    = (const float*)d_in[6];   // [20,384]
    const float* bf    = (const float*)d_in[7];   // [384]
    const float* W1    = (const float*)d_in[8];   // [128,128]
    const float* b1    = (const float*)d_in[9];   // [128]
    const float* W2    = (const float*)d_in[10];  // [128,384]
    const float* b2    = (const float*)d_in[11];  // [384]
    float* out = (float*)d_out;

    init_out_kernel<<<2560, 256>>>((const float4*)nss, (const float4*)nsv,
                                   (float4*)out);
    node_mlp_kernel<<<NUM_NODES / NB, 128>>>(nss, W1, b1, W2, b2);
    edge_kernel<<<NUM_EDGES / TE, 256>>>(
        nss, nsv, est, evec, edist, edges, Wf, bf, out);
}

// round 6
// speedup vs baseline: 1.0274x; 1.0274x over previous
#include <cuda_runtime.h>
#include <cuda_bf16.h>

#define NUM_NODES 20000
#define NUM_EDGES 640000
#define NODE 128
#define ESZ 20
#define F3 384          // 3 * NODE

typedef unsigned long long u64;

// ---- packed f32x2 helpers (SASS FFMA2 — PTX-only, ptxas won't auto-fuse) ----
__device__ __forceinline__ u64 pack2(float a, float b) {
    u64 r; asm("mov.b64 %0, {%1,%2};" : "=l"(r) : "f"(a), "f"(b)); return r;
}
__device__ __forceinline__ void unpack2(u64 v, float& a, float& b) {
    asm("mov.b64 {%0,%1}, %2;" : "=f"(a), "=f"(b) : "l"(v));
}
__device__ __forceinline__ u64 ffma2(u64 a, u64 b, u64 c) {
    u64 d; asm("fma.rn.f32x2 %0, %1, %2, %3;" : "=l"(d) : "l"(a), "l"(b), "l"(c));
    return d;
}

// scratch: scalar_output = silu(ns@W1+b1)@W2+b2, [NUM_NODES, 384]
__device__ float g_so[NUM_NODES * F3];

// ---------------------------------------------------------------------------
// Kernel 0: initialize output with the input node states (result = input + msum)
// ---------------------------------------------------------------------------
__global__ void init_out_kernel(const float4* __restrict__ nss,
                                const float4* __restrict__ nsv,
                                float4* __restrict__ out) {
    const int ns4 = NUM_NODES * NODE / 4;             // 640000
    const int tot4 = ns4 + NUM_NODES * 3 * NODE / 4;  // 2560000
    for (int i = blockIdx.x * blockDim.x + threadIdx.x; i < tot4;
         i += gridDim.x * blockDim.x) {
        out[i] = (i < ns4) ? nss[i] : nsv[i - ns4];
    }
}

// ---------------------------------------------------------------------------
// Kernel 1: node MLP -> g_so  (f32x2-packed over k pairs: even/odd split sum)
// ---------------------------------------------------------------------------
#define NB 8
__global__ __launch_bounds__(128) void node_mlp_kernel(
    const float* __restrict__ ns, const float* __restrict__ W1,
    const float* __restrict__ b1, const float* __restrict__ W2,
    const float* __restrict__ b2) {
    __shared__ float xs[NB][NODE];
    __shared__ float hs[NB][NODE];
    const int tid = threadIdx.x;
    const int base = blockIdx.x * NB;

    #pragma unroll
    for (int n = 0; n < NB; n++)
        xs[n][tid] = ns[(base + n) * NODE + tid];
    __syncthreads();

    // h = silu(x @ W1 + b1)
    {
        u64 acc[NB];
        const float bb = b1[tid];
        #pragma unroll
        for (int n = 0; n < NB; n++) acc[n] = pack2(bb, 0.0f);
        #pragma unroll 4
        for (int kp = 0; kp < NODE / 2; kp++) {
            const u64 w = pack2(W1[(2 * kp) * NODE + tid],
                                W1[(2 * kp + 1) * NODE + tid]);
            #pragma unroll
            for (int n = 0; n < NB; n++) {
                const u64 x = *(const u64*)&xs[n][2 * kp];   // LDS.64
                acc[n] = ffma2(x, w, acc[n]);
            }
        }
        #pragma unroll
        for (int n = 0; n < NB; n++) {
            float lo, hi; unpack2(acc[n], lo, hi);
            const float a = lo + hi;
            hs[n][tid] = a / (1.0f + __expf(-a));   // silu
        }
    }
    __syncthreads();

    // so = h @ W2 + b2   (384 outputs, 3 per thread)
    #pragma unroll
    for (int jj = 0; jj < 3; jj++) {
        const int j = tid + jj * NODE;
        u64 acc[NB];
        const float bb = b2[j];
        #pragma unroll
        for (int n = 0; n < NB; n++) acc[n] = pack2(bb, 0.0f);
        #pragma unroll 4
        for (int kp = 0; kp < NODE / 2; kp++) {
            const u64 w = pack2(W2[(2 * kp) * F3 + j],
                                W2[(2 * kp + 1) * F3 + j]);
            #pragma unroll
            for (int n = 0; n < NB; n++) {
                const u64 h2 = *(const u64*)&hs[n][2 * kp];
                acc[n] = ffma2(h2, w, acc[n]);
            }
        }
        #pragma unroll
        for (int n = 0; n < NB; n++) {
            float lo, hi; unpack2(acc[n], lo, hi);
            g_so[(base + n) * F3 + j] = lo + hi;
        }
    }
}

// ---------------------------------------------------------------------------
// helpers
// ---------------------------------------------------------------------------
__device__ __forceinline__ void red4(float* p, float4 v) {
    asm volatile("red.global.add.v4.f32 [%0], {%1,%2,%3,%4};"
                 :: "l"(p), "f"(v.x), "f"(v.y), "f"(v.z), "f"(v.w)
                 : "memory");
}
__device__ __forceinline__ float4 fma4(float a, float4 b, float4 c) {
    return make_float4(fmaf(a, b.x, c.x), fmaf(a, b.y, c.y),
                       fmaf(a, b.z, c.z), fmaf(a, b.w, c.w));
}
__device__ __forceinline__ float4 mul4(float4 a, float4 b) {
    return make_float4(a.x * b.x, a.y * b.y, a.z * b.z, a.w * b.w);
}
__device__ __forceinline__ float4 scale4(float4 a, float s) {
    return make_float4(a.x * s, a.y * s, a.z * s, a.w * s);
}

// ---------------------------------------------------------------------------
// Kernel 2: edge filter GEMM (f32x2) + gating + vectorized reduction scatter
//   - Wf/bf/128-edge edge_state tile staged in smem once per block
//   - 8 warps x 4 rounds x 4 edges = 128 edges per block
//   - GEMM accumulators held as packed f32x2 (FFMA2: 2x fp32 rate)
// ---------------------------------------------------------------------------
#define TE 128                 // edges per block
#define WE 4                   // edges per warp per round
#define ROUNDS 4               // 8 warps * 4 edges * 4 rounds = 128

__global__ __launch_bounds__(256) void edge_kernel(
    const float* __restrict__ nss, const float* __restrict__ nsv,
    const float* __restrict__ est, const float* __restrict__ evec,
    const float* __restrict__ edist, const int* __restrict__ edges,
    const float* __restrict__ Wf, const float* __restrict__ bf,
    float* __restrict__ out) {
    __shared__ float4 sWf[ESZ * 96];   // 20 rows x 96 float4 = 30720 B
    __shared__ float4 sBf[96];         // 1536 B
    __shared__ float  sEs[TE * ESZ];   // 10240 B

    const int tid = threadIdx.x;
    const int warp = tid >> 5;
    const int lane = tid & 31;
    const int eblock = blockIdx.x * TE;

    // cooperative staging (all loads coalesced)
    {
        const float4* wf4 = (const float4*)Wf;
        #pragma unroll
        for (int i = tid; i < ESZ * 96; i += 256) sWf[i] = wf4[i];
        if (tid < 96) sBf[tid] = ((const float4*)bf)[tid];
        #pragma unroll
        for (int i = tid; i < TE * ESZ; i += 256) sEs[i] = est[eblock * ESZ + i];
    }
    __syncthreads();

    const ulonglong2* sWf2 = (const ulonglong2*)sWf;
    const ulonglong2* sBf2 = (const ulonglong2*)sBf;

    const int c = lane * 4;  // column base within each 128-wide chunk
    float* outv = out + (long)NUM_NODES * NODE;

    for (int r = 0; r < ROUNDS; r++) {
        const int elocal = r * 32 + warp * WE;   // first local edge this warp

        // hoist per-edge metadata so the loads overlap the GEMM
        int   srcs[WE], dsts[WE];
        float dd[WE], ev0[WE], ev1[WE], ev2[WE];
        #pragma unroll
        for (int i = 0; i < WE; i++) {
            const long e = (long)eblock + elocal + i;
            srcs[i] = __ldg(&edges[2 * e]);
            dsts[i] = __ldg(&edges[2 * e + 1]);
            dd[i]   = __ldg(&edist[e]);
            ev0[i]  = __ldg(&evec[e * 3 + 0]);
            ev1[i]  = __ldg(&evec[e * 3 + 1]);
            ev2[i]  = __ldg(&evec[e * 3 + 2]);
        }

        // accumulators: WE edges x 3 chunks x 2 f32x2, init with bias
        u64 a0[WE][2], a1[WE][2], a2[WE][2];
        {
            const ulonglong2 b0 = sBf2[lane];
            const ulonglong2 b1v = sBf2[32 + lane];
            const ulonglong2 b2v = sBf2[64 + lane];
            #pragma unroll
            for (int i = 0; i < WE; i++) {
                a0[i][0] = b0.x;  a0[i][1] = b0.y;
                a1[i][0] = b1v.x; a1[i][1] = b1v.y;
                a2[i][0] = b2v.x; a2[i][1] = b2v.y;
            }
        }

        // filter GEMM: fw = es @ Wf + bf   (packed f32x2 FMAs)
        #pragma unroll
        for (int k = 0; k < ESZ; k++) {
            const ulonglong2 w0 = sWf2[k * 96 + lane];
            const ulonglong2 w1 = sWf2[k * 96 + 32 + lane];
            const ulonglong2 w2 = sWf2[k * 96 + 64 + lane];
            #pragma unroll
            for (int i = 0; i < WE; i++) {
                const float ek = sEs[(elocal + i) * ESZ + k];   // smem broadcast
                const u64 ek2 = pack2(ek, ek);
                a0[i][0] = ffma2(ek2, w0.x, a0[i][0]);
                a0[i][1] = ffma2(ek2, w0.y, a0[i][1]);
                a1[i][0] = ffma2(ek2, w1.x, a1[i][0]);
                a1[i][1] = ffma2(ek2, w1.y, a1[i][1]);
                a2[i][0] = ffma2(ek2, w2.x, a2[i][0]);
                a2[i][1] = ffma2(ek2, w2.y, a2[i][1]);
            }
        }

        // epilogue: gating + scatter, per edge
        #pragma unroll
        for (int i = 0; i < WE; i++) {
            const int src = srcs[i];
            const int dst = dsts[i];

            const float d = dd[i];
            const float cut = (d < 5.0f)
                ? 0.5f * (__cosf(d * (3.14159265358979f / 5.0f)) + 1.0f) : 0.0f;

            const float v0 = ev0[i], v1 = ev1[i], v2 = ev2[i];
            const float nrm = sqrtf(v0 * v0 + v1 * v1 + v2 * v2);
            const float inv = 1.0f / fmaxf(nrm, 1e-12f);
            const float env0 = v0 * inv, env1 = v1 * inv, env2 = v2 * inv;

            float4 fw0, fw1, fw2;
            unpack2(a0[i][0], fw0.x, fw0.y); unpack2(a0[i][1], fw0.z, fw0.w);
            unpack2(a1[i][0], fw1.x, fw1.y); unpack2(a1[i][1], fw1.z, fw1.w);
            unpack2(a2[i][0], fw2.x, fw2.y); unpack2(a2[i][1], fw2.z, fw2.w);

            // filter_output = fw * cut * scalar_output[src]  (cut folded)
            const float4* sop = (const float4*)&g_so[(long)src * F3];
            const float4 fo0 = mul4(fw0, scale4(sop[lane],      cut)); // gate_state_vector
            const float4 fo1 = mul4(fw1, scale4(sop[32 + lane], cut)); // gate_edge_vector
            const float4 fo2 = mul4(fw2, scale4(sop[64 + lane], cut)); // gate_node_state

            // scalar message
            const float4 nssv = ((const float4*)&nss[(long)src * NODE])[lane];
            red4(&out[(long)dst * NODE + c], mul4(nssv, fo2));

            // vector messages
            const float4* nvp = (const float4*)&nsv[(long)src * 3 * NODE];
            {
                float4 m = mul4(nvp[lane], fo0);      m = fma4(env0, fo1, m);
                red4(&outv[(long)dst * 3 * NODE + 0 * NODE + c], m);
            }
            {
                float4 m = mul4(nvp[32 + lane], fo0); m = fma4(env1, fo1, m);
                red4(&outv[(long)dst * 3 * NODE + 1 * NODE + c], m);
            }
            {
                float4 m = mul4(nvp[64 + lane], fo0); m = fma4(env2, fo1, m);
                red4(&outv[(long)dst * 3 * NODE + 2 * NODE + c], m);
            }
        }
    }
}

// ---------------------------------------------------------------------------
extern "C" void kernel_launch(void* const* d_in, const int* in_sizes, int n_in,
                              void* d_out, int out_size) {
    const float* nss   = (const float*)d_in[0];   // [20000,128]
    const float* nsv   = (const float*)d_in[1];   // [20000,3,128]
    const float* est   = (const float*)d_in[2];   // [640000,20]
    const float* evec  = (const float*)d_in[3];   // [640000,3]
    const float* edist = (const float*)d_in[4];   // [640000,1]
    const int*   edges = (const int*)d_in[5];     // [640000,2]
    const float* Wf    = (const float*)d_in[6];   // [20,384]
    const float* bf    = (const float*)d_in[7];   // [384]
    const float* W1    = (const float*)d_in[8];   // [128,128]
    const float* b1    = (const float*)d_in[9];   // [128]
    const float* W2    = (const float*)d_in[10];  // [128,384]
    const float* b2    = (const float*)d_in[11];  // [384]
    float* out = (float*)d_out;

    init_out_kernel<<<2560, 256>>>((const float4*)nss, (const float4*)nsv,
                                   (float4*)out);
    node_mlp_kernel<<<NUM_NODES / NB, 128>>>(nss, W1, b1, W2, b2);
    edge_kernel<<<NUM_EDGES / TE, 256>>>(
        nss, nsv, est, evec, edist, edges, Wf, bf, out);
}